// round 15
// baseline (speedup 1.0000x reference)
#include <cuda_runtime.h>
#include <cuda_fp16.h>
#include <cstdint>

#define N_NODES 50000
#define NNZ     800000
#define S       3
#define D_IN    512
#define D_OUT   256
#define N_ALL   (S * D_OUT)                    // 768

#define N_HIST      (S * N_NODES)              // 150000
#define SCAN_B      1024
#define SCAN_BLOCKS ((N_HIST + SCAN_B - 1) / SCAN_B)   // 147

// scratch
__device__ __half g_xh[(size_t)N_NODES * D_IN];          // fp16 x (51.2 MB)
__device__ __half g_wh[(size_t)S * D_IN * D_OUT];        // fp16 W [s][k][n]
__device__ uint2  g_pre2[(size_t)N_NODES * (N_ALL / 4)]; // fp16 pre [node][768]
__device__ int    g_hist[N_HIST];
__device__ int    g_off[N_HIST + 1];
__device__ int    g_cursor[N_HIST];
__device__ int    g_bsum[SCAN_BLOCKS];
__device__ int2   g_edges[(size_t)S * NNZ];    // (pre2-base-index, val-bits)

// ---------------------------------------------------------------------------
// Fused cvt(W)+cvt(x)+hist: block-range dispatch.  hist is L2-atomic bound,
// cvt is HBM-streaming -> disjoint pipes overlap in one launch.
// ---------------------------------------------------------------------------
#define CVTW_N4     (S * D_IN * D_OUT / 4)         // 98304
#define CVTX_N4     (N_NODES * D_IN / 4)           // 6400000
#define CVTW_BLOCKS (CVTW_N4 / 256)                // 384
#define CVTX_BLOCKS (CVTX_N4 / 256)                // 25000
#define HIST_BLOCKS ((S * NNZ) / 256)              // 9375
#define FUSED1_BLOCKS (CVTW_BLOCKS + CVTX_BLOCKS + HIST_BLOCKS)

__device__ __forceinline__ void cvt4(const float* __restrict__ in,
                                     __half* __restrict__ outp, int i)
{
    const float4 v = ((const float4*)in)[i];
    __half2 h0 = __floats2half2_rn(v.x, v.y);
    __half2 h1 = __floats2half2_rn(v.z, v.w);
    uint2 u;
    u.x = *(const uint32_t*)&h0;
    u.y = *(const uint32_t*)&h1;
    ((uint2*)outp)[i] = u;
}

__global__ __launch_bounds__(256) void fused_cvt_hist_kernel(
    const float* __restrict__ x,
    const float* __restrict__ W,
    const int*   __restrict__ rows)
{
    const int bid = blockIdx.x;
    const int tid = threadIdx.x;
    if (bid < CVTW_BLOCKS) {
        cvt4(W, g_wh, bid * 256 + tid);
    } else if (bid < CVTW_BLOCKS + CVTX_BLOCKS) {
        cvt4(x, g_xh, (bid - CVTW_BLOCKS) * 256 + tid);
    } else {
        const int i = (bid - CVTW_BLOCKS - CVTX_BLOCKS) * 256 + tid; // [0, S*NNZ)
        const int s = i / NNZ;
        atomicAdd(&g_hist[s * N_NODES + rows[i]], 1);
    }
}

// ---------------------------------------------------------------------------
// CSR build scaffolding
// ---------------------------------------------------------------------------
__global__ __launch_bounds__(256) void zero_hist_kernel()
{
    const int i = blockIdx.x * 256 + threadIdx.x;
    if (i < N_HIST) g_hist[i] = 0;
}

__global__ __launch_bounds__(SCAN_B) void scan_l1_kernel()
{
    __shared__ int sh[SCAN_B];
    const int tid = threadIdx.x;
    const int i   = blockIdx.x * SCAN_B + tid;
    const int v   = (i < N_HIST) ? g_hist[i] : 0;
    sh[tid] = v;
    __syncthreads();
#pragma unroll
    for (int d = 1; d < SCAN_B; d <<= 1) {
        const int t = (tid >= d) ? sh[tid - d] : 0;
        __syncthreads();
        sh[tid] += t;
        __syncthreads();
    }
    if (i < N_HIST) g_off[i] = sh[tid] - v;
    if (tid == SCAN_B - 1) g_bsum[blockIdx.x] = sh[tid];
}

__global__ __launch_bounds__(256) void scan_l2_kernel()
{
    __shared__ int sh[SCAN_BLOCKS];
    const int tid = threadIdx.x;
    for (int i = tid; i < SCAN_BLOCKS; i += 256) sh[i] = g_bsum[i];
    __syncthreads();
    if (tid == 0) {
        int run = 0;
        for (int i = 0; i < SCAN_BLOCKS; i++) { int t = sh[i]; sh[i] = run; run += t; }
    }
    __syncthreads();
    for (int i = tid; i < SCAN_BLOCKS; i += 256) g_bsum[i] = sh[i];
}

__global__ __launch_bounds__(SCAN_B) void scan_l3_kernel()
{
    const int i = blockIdx.x * SCAN_B + threadIdx.x;
    if (i < N_HIST) {
        const int v = g_off[i] + g_bsum[blockIdx.x];
        g_off[i]    = v;
        g_cursor[i] = v;
    }
    if (i == 0) g_off[N_HIST] = S * NNZ;
}

// ---------------------------------------------------------------------------
// Merged fp16 GEMM (fp32 accum) + fused scatter tail blocks.
//   pre[:, s*256:(s+1)*256] = cw[s]*(xh @ Wh[s]).  M=50000, N=768, K=512.
// BK=32, 4-stage cp.async, ldmatrix A + ldmatrix.trans B, mma.m16n8k16.
// 128x128 tile, 256 threads (2x4 warps), warp tile 64x32.
// Scatter: 722 appended blocks x 3328 edges (few waves at 2 CTA/SM; hides
// under the tensor-bound gemm blocks).
// ---------------------------------------------------------------------------
#define BM 128
#define BN 128
#define BK 32
#define STAGES 4
#define A_ROW_H   40                      // halves per A row (32 + 8 pad)
#define A_STAGE_B (BM * A_ROW_H * 2)      // 10240 bytes
#define B_ROW_H   136                     // halves per B row (128 + 8 pad)
#define B_STAGE_B (BK * B_ROW_H * 2)      // 8704 bytes
#define GEMM_SMEM_BYTES (STAGES * (A_STAGE_B + B_STAGE_B))   // 75776

#define GEMM_BX 6
#define GEMM_BLOCKS (GEMM_BX * ((N_NODES + BM - 1) / BM))    // 2346
#define EDGES_PER_BLK 3328
#define SCAT_BLOCKS ((S * NNZ + EDGES_PER_BLK - 1) / EDGES_PER_BLK)  // 722

__device__ __forceinline__ void cp16(uint32_t dst, const void* src, int bytes)
{
    asm volatile("cp.async.cg.shared.global [%0], [%1], 16, %2;\n"
                 :: "r"(dst), "l"(src), "r"(bytes));
}
#define CP_COMMIT() asm volatile("cp.async.commit_group;\n" ::: "memory")
#define CP_WAIT2()  asm volatile("cp.async.wait_group 2;\n"  ::: "memory")

__device__ __forceinline__ void ldsm_x4(uint32_t& d0, uint32_t& d1,
                                        uint32_t& d2, uint32_t& d3, uint32_t addr)
{
    asm volatile("ldmatrix.sync.aligned.m8n8.x4.shared.b16 {%0,%1,%2,%3}, [%4];\n"
                 : "=r"(d0), "=r"(d1), "=r"(d2), "=r"(d3) : "r"(addr));
}

__device__ __forceinline__ void ldsm_x4t(uint32_t& d0, uint32_t& d1,
                                         uint32_t& d2, uint32_t& d3, uint32_t addr)
{
    asm volatile("ldmatrix.sync.aligned.m8n8.x4.trans.shared.b16 {%0,%1,%2,%3}, [%4];\n"
                 : "=r"(d0), "=r"(d1), "=r"(d2), "=r"(d3) : "r"(addr));
}

__device__ __forceinline__ void mma_f16(float c[4], const uint32_t a[4], const uint32_t b[2])
{
    asm volatile(
        "mma.sync.aligned.m16n8k16.row.col.f32.f16.f16.f32 "
        "{%0,%1,%2,%3}, {%4,%5,%6,%7}, {%8,%9}, {%0,%1,%2,%3};\n"
        : "+f"(c[0]), "+f"(c[1]), "+f"(c[2]), "+f"(c[3])
        : "r"(a[0]), "r"(a[1]), "r"(a[2]), "r"(a[3]),
          "r"(b[0]), "r"(b[1]));
}

__global__ __launch_bounds__(256, 2) void gemm_scatter_kernel(
    const __half* __restrict__ xh,
    const __half* __restrict__ wh,
    const float*  __restrict__ cw,
    const int*    __restrict__ rows,
    const int*    __restrict__ cols,
    const float*  __restrict__ vals)
{
    // ---- scatter tail blocks ----
    if (blockIdx.x >= GEMM_BLOCKS) {
        const int base = (blockIdx.x - GEMM_BLOCKS) * EDGES_PER_BLK;
#pragma unroll
        for (int k = 0; k < EDGES_PER_BLK / 256; k++) {
            const int i = base + k * 256 + threadIdx.x;
            if (i < S * NNZ) {
                const int s = i / NNZ;
                const int r = rows[i];
                const int pos = atomicAdd(&g_cursor[s * N_NODES + r], 1);
                g_edges[pos] = make_int2(cols[i] * (N_ALL / 4) + s * (D_OUT / 4),
                                         __float_as_int(vals[i]));
            }
        }
        return;
    }

    // ---- gemm blocks ----
    extern __shared__ char smc[];
    const uint32_t sm_u32 = (uint32_t)__cvta_generic_to_shared(smc);

    const int block_row = (blockIdx.x / GEMM_BX) * BM;
    const int block_col = (blockIdx.x % GEMM_BX) * BN;   // 0..767
    const int s         = block_col >> 8;
    const int col_in_s  = block_col & 255;
    const int tid  = threadIdx.x;
    const int lane = tid & 31;
    const int wid  = tid >> 5;
    const int warp_m = wid >> 2;   // 0..1
    const int warp_n = wid & 3;    // 0..3

    const __half* Bg = wh + (size_t)s * D_IN * D_OUT + col_in_s;

    // cp.async mappings: A = 128 rows x 4 chunks(16B=8 halves), 2 per thread
    const int a_row0 = tid >> 2;   // 0..63 (+64)
    const int a_ch   = tid & 3;
    // B = 32 k-rows x 16 chunks, 2 per thread
    const int b_kr0  = tid >> 4;   // 0..15 (+16)
    const int b_nc   = tid & 15;

    // ldmatrix address lanes
    const int l_r  = lane & 7;
    const int l_b1 = (lane >> 3) & 1;
    const int l_b2 = lane >> 4;

    float c[4][4][4];
#pragma unroll
    for (int mt = 0; mt < 4; mt++)
#pragma unroll
        for (int nt = 0; nt < 4; nt++)
#pragma unroll
            for (int i = 0; i < 4; i++) c[mt][nt][i] = 0.0f;

    auto load_stage = [&](int st, int k0) {
        const uint32_t a_base = sm_u32 + (uint32_t)(st * A_STAGE_B);
        const uint32_t b_base = sm_u32 + (uint32_t)(STAGES * A_STAGE_B + st * B_STAGE_B);
#pragma unroll
        for (int h = 0; h < 2; h++) {
            const int row  = a_row0 + h * 64;
            const int grow = block_row + row;
            const int vrow = (grow < N_NODES) ? grow : (N_NODES - 1);
            const __half* src = xh + (size_t)vrow * D_IN + k0 + a_ch * 8;
            cp16(a_base + (uint32_t)(row * A_ROW_H + a_ch * 8) * 2u, src,
                 (grow < N_NODES) ? 16 : 0);
        }
#pragma unroll
        for (int h = 0; h < 2; h++) {
            const int kr = b_kr0 + h * 16;
            const __half* src = Bg + (size_t)(k0 + kr) * D_OUT + b_nc * 8;
            cp16(b_base + (uint32_t)(kr * B_ROW_H + b_nc * 8) * 2u, src, 16);
        }
    };

    load_stage(0, 0);  CP_COMMIT();
    load_stage(1, 32); CP_COMMIT();
    load_stage(2, 64); CP_COMMIT();

    const int NITER = D_IN / BK;   // 16
    for (int it = 0; it < NITER; it++) {
        CP_WAIT2();
        __syncthreads();

        const int nk = (it + 3) * BK;
        if (nk < D_IN) load_stage((it + 3) & 3, nk);
        CP_COMMIT();

        const int st = it & 3;
        const uint32_t a_base = sm_u32 + (uint32_t)(st * A_STAGE_B);
        const uint32_t b_base = sm_u32 + (uint32_t)(STAGES * A_STAGE_B + st * B_STAGE_B);

#pragma unroll
        for (int kh = 0; kh < 2; kh++) {            // k16 step
            uint32_t a[4][4];
            uint32_t b[4][2];
#pragma unroll
            for (int mt = 0; mt < 4; mt++) {
                const int row = warp_m * 64 + mt * 16 + l_b1 * 8 + l_r;
                const int col = kh * 16 + l_b2 * 8;
                ldsm_x4(a[mt][0], a[mt][1], a[mt][2], a[mt][3],
                        a_base + (uint32_t)(row * A_ROW_H + col) * 2u);
            }
#pragma unroll
            for (int half = 0; half < 2; half++) {
                const int kr  = kh * 16 + l_b1 * 8 + l_r;
                const int ncl = warp_n * 32 + half * 16 + l_b2 * 8;
                uint32_t r0, r1, r2, r3;
                ldsm_x4t(r0, r1, r2, r3,
                         b_base + (uint32_t)(kr * B_ROW_H + ncl) * 2u);
                b[half * 2 + 0][0] = r0; b[half * 2 + 0][1] = r1;
                b[half * 2 + 1][0] = r2; b[half * 2 + 1][1] = r3;
            }
#pragma unroll
            for (int mt = 0; mt < 4; mt++)
#pragma unroll
                for (int nt = 0; nt < 4; nt++)
                    mma_f16(c[mt][nt], a[mt], b[nt]);
        }
    }

    // epilogue: scale by cw[s], write pre (row stride 768) as fp16 half2
    const float scale = __ldg(cw + s);
    __half2* dst = (__half2*)g_pre2;

#pragma unroll
    for (int mt = 0; mt < 4; mt++) {
        const int r0 = block_row + warp_m * 64 + mt * 16 + (lane >> 2);
        const int r1 = r0 + 8;
#pragma unroll
        for (int nt = 0; nt < 4; nt++) {
            const int col = block_col + warp_n * 32 + nt * 8 + 2 * (lane & 3);
            if (r0 < N_NODES) {
                dst[((size_t)r0 * N_ALL + col) >> 1] =
                    __floats2half2_rn(c[mt][nt][0] * scale, c[mt][nt][1] * scale);
            }
            if (r1 < N_NODES) {
                dst[((size_t)r1 * N_ALL + col) >> 1] =
                    __floats2half2_rn(c[mt][nt][2] * scale, c[mt][nt][3] * scale);
            }
        }
    }
}

// ---------------------------------------------------------------------------
// Merged CSR gather over all 3 supports + relu, single out write.
// ---------------------------------------------------------------------------
__global__ __launch_bounds__(256) void gather_kernel(float* __restrict__ out)
{
    const int r    = blockIdx.x * 4 + (threadIdx.x >> 6);   // [0, N_NODES)
    const int lane = threadIdx.x & 63;

    float4 acc = make_float4(0.f, 0.f, 0.f, 0.f);

#pragma unroll
    for (int s = 0; s < S; s++) {
        const int beg = g_off[s * N_NODES + r];
        const int end = g_off[s * N_NODES + r + 1];
#pragma unroll 4
        for (int e = beg; e < end; e++) {
            const int2  ed = __ldg(&g_edges[e]);
            const float v  = __int_as_float(ed.y);
            const uint2 raw = g_pre2[(size_t)ed.x + lane];
            const float2 f0 = __half22float2(*(const __half2*)&raw.x);
            const float2 f1 = __half22float2(*(const __half2*)&raw.y);
            acc.x = fmaf(v, f0.x, acc.x);
            acc.y = fmaf(v, f0.y, acc.y);
            acc.z = fmaf(v, f1.x, acc.z);
            acc.w = fmaf(v, f1.y, acc.w);
        }
    }

    acc.x = fmaxf(acc.x, 0.f);
    acc.y = fmaxf(acc.y, 0.f);
    acc.z = fmaxf(acc.z, 0.f);
    acc.w = fmaxf(acc.w, 0.f);
    ((float4*)out)[(size_t)r * 64 + lane] = acc;
}

// ---------------------------------------------------------------------------
// Launch (fused gemm+scatter at profiled launch index 5)
// ---------------------------------------------------------------------------
extern "C" void kernel_launch(void* const* d_in, const int* in_sizes, int n_in,
                              void* d_out, int out_size)
{
    const float* x    = (const float*)d_in[0];
    const float* W    = (const float*)d_in[1];
    const int*   rows = (const int*)d_in[2];
    const int*   cols = (const int*)d_in[3];
    const float* vals = (const float*)d_in[4];
    const float* cw   = (const float*)d_in[5];
    float*       out  = (float*)d_out;

    __half *xh, *wh;
    cudaGetSymbolAddress((void**)&xh, g_xh);
    cudaGetSymbolAddress((void**)&wh, g_wh);

    cudaFuncSetAttribute(gemm_scatter_kernel,
                         cudaFuncAttributeMaxDynamicSharedMemorySize,
                         GEMM_SMEM_BYTES);

    zero_hist_kernel<<<(N_HIST + 255) / 256, 256>>>();                 // 0
    fused_cvt_hist_kernel<<<FUSED1_BLOCKS, 256>>>(x, W, rows);         // 1
    scan_l1_kernel<<<SCAN_BLOCKS, SCAN_B>>>();                         // 2
    scan_l2_kernel<<<1, 256>>>();                                      // 3
    scan_l3_kernel<<<SCAN_BLOCKS, SCAN_B>>>();                         // 4

    gemm_scatter_kernel<<<GEMM_BLOCKS + SCAT_BLOCKS, 256,              // 5
                          GEMM_SMEM_BYTES>>>(xh, wh, cw, rows, cols, vals);

    gather_kernel<<<12500, 256>>>(out);                                // 6
}

// round 16
// speedup vs baseline: 1.4007x; 1.4007x over previous
#include <cuda_runtime.h>
#include <cuda_fp16.h>
#include <cstdint>

#define N_NODES 50000
#define NNZ     800000
#define S       3
#define D_IN    512
#define D_OUT   256
#define N_ALL   (S * D_OUT)                    // 768

#define N_HIST      (S * N_NODES)              // 150000
#define SCAN_B      1024
#define SCAN_BLOCKS ((N_HIST + SCAN_B - 1) / SCAN_B)   // 147

// scratch
__device__ __half g_xh[(size_t)N_NODES * D_IN];          // fp16 x (51.2 MB)
__device__ __half g_wh[(size_t)S * D_IN * D_OUT];        // fp16 W [s][k][n]
__device__ uint2  g_pre2[(size_t)N_NODES * (N_ALL / 4)]; // fp16 pre [node][768]
__device__ int    g_hist[N_HIST];
__device__ int    g_off[N_HIST + 1];
__device__ int    g_cursor[N_HIST];
__device__ int    g_bsum[SCAN_BLOCKS];
__device__ int2   g_edges[(size_t)S * NNZ];    // (pre2-base-index, val-bits)

// ---------------------------------------------------------------------------
// Fused cvt(W)+cvt(x)+hist: block-range dispatch.  hist is L2-atomic bound,
// cvt is HBM-streaming -> disjoint pipes overlap in one launch.
// ---------------------------------------------------------------------------
#define CVTW_N4     (S * D_IN * D_OUT / 4)         // 98304
#define CVTX_N4     (N_NODES * D_IN / 4)           // 6400000
#define CVTW_BLOCKS (CVTW_N4 / 256)                // 384
#define CVTX_BLOCKS (CVTX_N4 / 256)                // 25000
#define HIST_BLOCKS ((S * NNZ) / 256)              // 9375
#define FUSED1_BLOCKS (CVTW_BLOCKS + CVTX_BLOCKS + HIST_BLOCKS)

__device__ __forceinline__ void cvt4(const float* __restrict__ in,
                                     __half* __restrict__ outp, int i)
{
    const float4 v = ((const float4*)in)[i];
    __half2 h0 = __floats2half2_rn(v.x, v.y);
    __half2 h1 = __floats2half2_rn(v.z, v.w);
    uint2 u;
    u.x = *(const uint32_t*)&h0;
    u.y = *(const uint32_t*)&h1;
    ((uint2*)outp)[i] = u;
}

__global__ __launch_bounds__(256) void fused_cvt_hist_kernel(
    const float* __restrict__ x,
    const float* __restrict__ W,
    const int*   __restrict__ rows)
{
    const int bid = blockIdx.x;
    const int tid = threadIdx.x;
    if (bid < CVTW_BLOCKS) {
        cvt4(W, g_wh, bid * 256 + tid);
    } else if (bid < CVTW_BLOCKS + CVTX_BLOCKS) {
        cvt4(x, g_xh, (bid - CVTW_BLOCKS) * 256 + tid);
    } else {
        const int i = (bid - CVTW_BLOCKS - CVTX_BLOCKS) * 256 + tid; // [0, S*NNZ)
        const int s = i / NNZ;
        atomicAdd(&g_hist[s * N_NODES + rows[i]], 1);
    }
}

// ---------------------------------------------------------------------------
// CSR build scaffolding
// ---------------------------------------------------------------------------
__global__ __launch_bounds__(256) void zero_hist_kernel()
{
    const int i = blockIdx.x * 256 + threadIdx.x;
    if (i < N_HIST) g_hist[i] = 0;
}

__global__ __launch_bounds__(SCAN_B) void scan_l1_kernel()
{
    __shared__ int sh[SCAN_B];
    const int tid = threadIdx.x;
    const int i   = blockIdx.x * SCAN_B + tid;
    const int v   = (i < N_HIST) ? g_hist[i] : 0;
    sh[tid] = v;
    __syncthreads();
#pragma unroll
    for (int d = 1; d < SCAN_B; d <<= 1) {
        const int t = (tid >= d) ? sh[tid - d] : 0;
        __syncthreads();
        sh[tid] += t;
        __syncthreads();
    }
    if (i < N_HIST) g_off[i] = sh[tid] - v;
    if (tid == SCAN_B - 1) g_bsum[blockIdx.x] = sh[tid];
}

__global__ __launch_bounds__(256) void scan_l2_kernel()
{
    __shared__ int sh[SCAN_BLOCKS];
    const int tid = threadIdx.x;
    for (int i = tid; i < SCAN_BLOCKS; i += 256) sh[i] = g_bsum[i];
    __syncthreads();
    if (tid == 0) {
        int run = 0;
        for (int i = 0; i < SCAN_BLOCKS; i++) { int t = sh[i]; sh[i] = run; run += t; }
    }
    __syncthreads();
    for (int i = tid; i < SCAN_BLOCKS; i += 256) g_bsum[i] = sh[i];
}

__global__ __launch_bounds__(SCAN_B) void scan_l3_kernel()
{
    const int i = blockIdx.x * SCAN_B + threadIdx.x;
    if (i < N_HIST) {
        const int v = g_off[i] + g_bsum[blockIdx.x];
        g_off[i]    = v;
        g_cursor[i] = v;
    }
    if (i == 0) g_off[N_HIST] = S * NNZ;
}

__global__ __launch_bounds__(256) void scatter_kernel(
    const int*   __restrict__ rows,
    const int*   __restrict__ cols,
    const float* __restrict__ vals)
{
    const int i = blockIdx.x * 256 + threadIdx.x;   // [0, S*NNZ)
    const int s = i / NNZ;
    const int r = rows[i];
    const int pos = atomicAdd(&g_cursor[s * N_NODES + r], 1);
    g_edges[pos] = make_int2(cols[i] * (N_ALL / 4) + s * (D_OUT / 4),
                             __float_as_int(vals[i]));
}

// ---------------------------------------------------------------------------
// Merged fp16 GEMM (fp32 accum): pre[:, s*256:(s+1)*256] = cw[s]*(xh @ Wh[s]).
// M=50000, N=768, K=512.  BK=32, 4-stage cp.async, ldmatrix A + ldmatrix.trans B,
// mma.m16n8k16.  128x128 tile, 256 threads (2x4 warps), warp tile 64x32.
// (Standalone kernel — exact R13 resource envelope, 2 CTAs/SM.)
// ---------------------------------------------------------------------------
#define BM 128
#define BN 128
#define BK 32
#define STAGES 4
#define A_ROW_H   40                      // halves per A row (32 + 8 pad)
#define A_STAGE_B (BM * A_ROW_H * 2)      // 10240 bytes
#define B_ROW_H   136                     // halves per B row (128 + 8 pad)
#define B_STAGE_B (BK * B_ROW_H * 2)      // 8704 bytes
#define GEMM_SMEM_BYTES (STAGES * (A_STAGE_B + B_STAGE_B))   // 75776

__device__ __forceinline__ void cp16(uint32_t dst, const void* src, int bytes)
{
    asm volatile("cp.async.cg.shared.global [%0], [%1], 16, %2;\n"
                 :: "r"(dst), "l"(src), "r"(bytes));
}
#define CP_COMMIT() asm volatile("cp.async.commit_group;\n" ::: "memory")
#define CP_WAIT2()  asm volatile("cp.async.wait_group 2;\n"  ::: "memory")

__device__ __forceinline__ void ldsm_x4(uint32_t& d0, uint32_t& d1,
                                        uint32_t& d2, uint32_t& d3, uint32_t addr)
{
    asm volatile("ldmatrix.sync.aligned.m8n8.x4.shared.b16 {%0,%1,%2,%3}, [%4];\n"
                 : "=r"(d0), "=r"(d1), "=r"(d2), "=r"(d3) : "r"(addr));
}

__device__ __forceinline__ void ldsm_x4t(uint32_t& d0, uint32_t& d1,
                                         uint32_t& d2, uint32_t& d3, uint32_t addr)
{
    asm volatile("ldmatrix.sync.aligned.m8n8.x4.trans.shared.b16 {%0,%1,%2,%3}, [%4];\n"
                 : "=r"(d0), "=r"(d1), "=r"(d2), "=r"(d3) : "r"(addr));
}

__device__ __forceinline__ void mma_f16(float c[4], const uint32_t a[4], const uint32_t b[2])
{
    asm volatile(
        "mma.sync.aligned.m16n8k16.row.col.f32.f16.f16.f32 "
        "{%0,%1,%2,%3}, {%4,%5,%6,%7}, {%8,%9}, {%0,%1,%2,%3};\n"
        : "+f"(c[0]), "+f"(c[1]), "+f"(c[2]), "+f"(c[3])
        : "r"(a[0]), "r"(a[1]), "r"(a[2]), "r"(a[3]),
          "r"(b[0]), "r"(b[1]));
}

__global__ __launch_bounds__(256, 2) void gemm_f16_kernel(
    const __half* __restrict__ xh,
    const __half* __restrict__ wh,
    const float*  __restrict__ cw)
{
    extern __shared__ char smc[];
    const uint32_t sm_u32 = (uint32_t)__cvta_generic_to_shared(smc);

    const int block_row = blockIdx.y * BM;
    const int block_col = blockIdx.x * BN;      // 0..767
    const int s         = block_col >> 8;
    const int col_in_s  = block_col & 255;
    const int tid  = threadIdx.x;
    const int lane = tid & 31;
    const int wid  = tid >> 5;
    const int warp_m = wid >> 2;   // 0..1
    const int warp_n = wid & 3;    // 0..3

    const __half* Bg = wh + (size_t)s * D_IN * D_OUT + col_in_s;

    const int a_row0 = tid >> 2;   // 0..63 (+64)
    const int a_ch   = tid & 3;
    const int b_kr0  = tid >> 4;   // 0..15 (+16)
    const int b_nc   = tid & 15;

    const int l_r  = lane & 7;
    const int l_b1 = (lane >> 3) & 1;
    const int l_b2 = lane >> 4;

    float c[4][4][4];
#pragma unroll
    for (int mt = 0; mt < 4; mt++)
#pragma unroll
        for (int nt = 0; nt < 4; nt++)
#pragma unroll
            for (int i = 0; i < 4; i++) c[mt][nt][i] = 0.0f;

    auto load_stage = [&](int st, int k0) {
        const uint32_t a_base = sm_u32 + (uint32_t)(st * A_STAGE_B);
        const uint32_t b_base = sm_u32 + (uint32_t)(STAGES * A_STAGE_B + st * B_STAGE_B);
#pragma unroll
        for (int h = 0; h < 2; h++) {
            const int row  = a_row0 + h * 64;
            const int grow = block_row + row;
            const int vrow = (grow < N_NODES) ? grow : (N_NODES - 1);
            const __half* src = xh + (size_t)vrow * D_IN + k0 + a_ch * 8;
            cp16(a_base + (uint32_t)(row * A_ROW_H + a_ch * 8) * 2u, src,
                 (grow < N_NODES) ? 16 : 0);
        }
#pragma unroll
        for (int h = 0; h < 2; h++) {
            const int kr = b_kr0 + h * 16;
            const __half* src = Bg + (size_t)(k0 + kr) * D_OUT + b_nc * 8;
            cp16(b_base + (uint32_t)(kr * B_ROW_H + b_nc * 8) * 2u, src, 16);
        }
    };

    load_stage(0, 0);  CP_COMMIT();
    load_stage(1, 32); CP_COMMIT();
    load_stage(2, 64); CP_COMMIT();

    const int NITER = D_IN / BK;   // 16
    for (int it = 0; it < NITER; it++) {
        CP_WAIT2();
        __syncthreads();

        const int nk = (it + 3) * BK;
        if (nk < D_IN) load_stage((it + 3) & 3, nk);
        CP_COMMIT();

        const int st = it & 3;
        const uint32_t a_base = sm_u32 + (uint32_t)(st * A_STAGE_B);
        const uint32_t b_base = sm_u32 + (uint32_t)(STAGES * A_STAGE_B + st * B_STAGE_B);

#pragma unroll
        for (int kh = 0; kh < 2; kh++) {            // k16 step
            uint32_t a[4][4];
            uint32_t b[4][2];
#pragma unroll
            for (int mt = 0; mt < 4; mt++) {
                const int row = warp_m * 64 + mt * 16 + l_b1 * 8 + l_r;
                const int col = kh * 16 + l_b2 * 8;
                ldsm_x4(a[mt][0], a[mt][1], a[mt][2], a[mt][3],
                        a_base + (uint32_t)(row * A_ROW_H + col) * 2u);
            }
#pragma unroll
            for (int half = 0; half < 2; half++) {
                const int kr  = kh * 16 + l_b1 * 8 + l_r;
                const int ncl = warp_n * 32 + half * 16 + l_b2 * 8;
                uint32_t r0, r1, r2, r3;
                ldsm_x4t(r0, r1, r2, r3,
                         b_base + (uint32_t)(kr * B_ROW_H + ncl) * 2u);
                b[half * 2 + 0][0] = r0; b[half * 2 + 0][1] = r1;
                b[half * 2 + 1][0] = r2; b[half * 2 + 1][1] = r3;
            }
#pragma unroll
            for (int mt = 0; mt < 4; mt++)
#pragma unroll
                for (int nt = 0; nt < 4; nt++)
                    mma_f16(c[mt][nt], a[mt], b[nt]);
        }
    }

    // epilogue: scale by cw[s], write pre (row stride 768) as fp16 half2
    const float scale = __ldg(cw + s);
    __half2* dst = (__half2*)g_pre2;

#pragma unroll
    for (int mt = 0; mt < 4; mt++) {
        const int r0 = block_row + warp_m * 64 + mt * 16 + (lane >> 2);
        const int r1 = r0 + 8;
#pragma unroll
        for (int nt = 0; nt < 4; nt++) {
            const int col = block_col + warp_n * 32 + nt * 8 + 2 * (lane & 3);
            if (r0 < N_NODES) {
                dst[((size_t)r0 * N_ALL + col) >> 1] =
                    __floats2half2_rn(c[mt][nt][0] * scale, c[mt][nt][1] * scale);
            }
            if (r1 < N_NODES) {
                dst[((size_t)r1 * N_ALL + col) >> 1] =
                    __floats2half2_rn(c[mt][nt][2] * scale, c[mt][nt][3] * scale);
            }
        }
    }
}

// ---------------------------------------------------------------------------
// Merged CSR gather over all 3 supports + relu, single out write.
// ---------------------------------------------------------------------------
__global__ __launch_bounds__(256) void gather_kernel(float* __restrict__ out)
{
    const int r    = blockIdx.x * 4 + (threadIdx.x >> 6);   // [0, N_NODES)
    const int lane = threadIdx.x & 63;

    float4 acc = make_float4(0.f, 0.f, 0.f, 0.f);

#pragma unroll
    for (int s = 0; s < S; s++) {
        const int beg = g_off[s * N_NODES + r];
        const int end = g_off[s * N_NODES + r + 1];
#pragma unroll 4
        for (int e = beg; e < end; e++) {
            const int2  ed = __ldg(&g_edges[e]);
            const float v  = __int_as_float(ed.y);
            const uint2 raw = g_pre2[(size_t)ed.x + lane];
            const float2 f0 = __half22float2(*(const __half2*)&raw.x);
            const float2 f1 = __half22float2(*(const __half2*)&raw.y);
            acc.x = fmaf(v, f0.x, acc.x);
            acc.y = fmaf(v, f0.y, acc.y);
            acc.z = fmaf(v, f1.x, acc.z);
            acc.w = fmaf(v, f1.y, acc.w);
        }
    }

    acc.x = fmaxf(acc.x, 0.f);
    acc.y = fmaxf(acc.y, 0.f);
    acc.z = fmaxf(acc.z, 0.f);
    acc.w = fmaxf(acc.w, 0.f);
    ((float4*)out)[(size_t)r * 64 + lane] = acc;
}

// ---------------------------------------------------------------------------
// Launch (gemm at profiled launch index 5)
// ---------------------------------------------------------------------------
extern "C" void kernel_launch(void* const* d_in, const int* in_sizes, int n_in,
                              void* d_out, int out_size)
{
    const float* x    = (const float*)d_in[0];
    const float* W    = (const float*)d_in[1];
    const int*   rows = (const int*)d_in[2];
    const int*   cols = (const int*)d_in[3];
    const float* vals = (const float*)d_in[4];
    const float* cw   = (const float*)d_in[5];
    float*       out  = (float*)d_out;

    __half *xh, *wh;
    cudaGetSymbolAddress((void**)&xh, g_xh);
    cudaGetSymbolAddress((void**)&wh, g_wh);

    cudaFuncSetAttribute(gemm_f16_kernel,
                         cudaFuncAttributeMaxDynamicSharedMemorySize,
                         GEMM_SMEM_BYTES);

    zero_hist_kernel<<<(N_HIST + 255) / 256, 256>>>();                 // 0
    fused_cvt_hist_kernel<<<FUSED1_BLOCKS, 256>>>(x, W, rows);         // 1
    scan_l1_kernel<<<SCAN_BLOCKS, SCAN_B>>>();                         // 2
    scan_l2_kernel<<<1, 256>>>();                                      // 3
    scan_l3_kernel<<<SCAN_BLOCKS, SCAN_B>>>();                         // 4

    dim3 ggrid(N_ALL / BN, (N_NODES + BM - 1) / BM);  // (6, 391)
    gemm_f16_kernel<<<ggrid, 256, GEMM_SMEM_BYTES>>>(xh, wh, cw);      // 5

    scatter_kernel<<<(S * NNZ) / 256, 256>>>(rows, cols, vals);        // 6
    gather_kernel<<<12500, 256>>>(out);                                // 7
}